// round 2
// baseline (speedup 1.0000x reference)
#include <cuda_runtime.h>
#include <cstdint>
#include <cstddef>

#define TOKENS 1024
#define HIDDEN 2048
#define INTER  4096
#define NEXP   8
#define BK 32
#define SA 36            // smem row stride in floats (144B: 16B aligned, conflict-free)
#define NTH 128

// ---------------- device scratch (allocation-free) ----------------
__device__ int   g_count[NEXP];
__device__ int   g_tok[NEXP][TOKENS];
__device__ float g_w[NEXP][TOKENS];
__device__ float g_act[(size_t)NEXP * TOKENS * INTER];   // [E][T][I] fp32

// ---------------- helpers ----------------
__device__ __forceinline__ uint32_t f2tf32(float f) {
    uint32_t u;
    asm("cvt.rna.tf32.f32 %0, %1;" : "=r"(u) : "f"(f));
    return u;
}

__device__ __forceinline__ void mma_tf32(float c[4],
                                         uint32_t a0, uint32_t a1, uint32_t a2, uint32_t a3,
                                         uint32_t b0, uint32_t b1) {
    asm volatile(
        "mma.sync.aligned.m16n8k8.row.col.f32.tf32.tf32.f32 "
        "{%0,%1,%2,%3}, {%4,%5,%6,%7}, {%8,%9}, {%0,%1,%2,%3};\n"
        : "+f"(c[0]), "+f"(c[1]), "+f"(c[2]), "+f"(c[3])
        : "r"(a0), "r"(a1), "r"(a2), "r"(a3), "r"(b0), "r"(b1));
}

__device__ __forceinline__ void cp16(uint32_t dst, const float* src, bool pred) {
    int sz = pred ? 16 : 0;
    asm volatile("cp.async.cg.shared.global [%0], [%1], 16, %2;\n"
                 :: "r"(dst), "l"(src), "r"(sz));
}
__device__ __forceinline__ void cp_commit() {
    asm volatile("cp.async.commit_group;\n");
}
__device__ __forceinline__ void cp_wait1() {
    asm volatile("cp.async.wait_group 1;\n");
}

// ---------------- kernel 0: zero out + counts ----------------
__global__ void zero_kernel(float* __restrict__ out) {
    int i = blockIdx.x * blockDim.x + threadIdx.x;
    reinterpret_cast<float4*>(out)[i] = make_float4(0.f, 0.f, 0.f, 0.f);
    if (blockIdx.x == 0 && threadIdx.x < NEXP) g_count[threadIdx.x] = 0;
}

// ---------------- kernel 1: router ----------------
__global__ void router_kernel(const float* __restrict__ logits) {
    int t = blockIdx.x * blockDim.x + threadIdx.x;
    if (t >= TOKENS) return;
    float l[NEXP];
#pragma unroll
    for (int j = 0; j < NEXP; j++) l[j] = logits[t * NEXP + j];
    int i0 = 0;
#pragma unroll
    for (int j = 1; j < NEXP; j++) if (l[j] > l[i0]) i0 = j;
    int i1 = -1;
#pragma unroll
    for (int j = 0; j < NEXP; j++) {
        if (j == i0) continue;
        if (i1 < 0 || l[j] > l[i1]) i1 = j;
    }
    float e1 = __expf(l[i1] - l[i0]);
    float w1 = e1 / (1.f + e1);
    float w0 = 1.f / (1.f + e1);
    int p0 = atomicAdd(&g_count[i0], 1);
    g_tok[i0][p0] = t;  g_w[i0][p0] = w0;
    int p1 = atomicAdd(&g_count[i1], 1);
    g_tok[i1][p1] = t;  g_w[i1][p1] = w1;
}

// =================================================================
// kernel 2: grouped GEMM1  (X gathered @ W13^T), SwiGLU -> g_act
// BM=128, BN=64 (gate) + paired up tile; 4 warps, warp tile 64x32 dual.
// =================================================================
#define G1_BUF ((128 + 64 + 64) * SA)   // floats per stage

__global__ void __launch_bounds__(NTH)
gemm1_kernel(const float* __restrict__ X, const float* __restrict__ W13) {
    const int e = blockIdx.z;
    const int ne = g_count[e];
    const int row0 = blockIdx.y * 128;
    if (row0 >= ne) return;
    const int col0 = blockIdx.x * 64;

    extern __shared__ float sm[];
    const uint32_t smBase = (uint32_t)__cvta_generic_to_shared(sm);

    const int tid = threadIdx.x, warp = tid >> 5, lane = tid & 31;
    const int g = lane >> 2, t4 = lane & 3;
    const int wm = (warp >> 1) * 64, wn = (warp & 1) * 32;
    const int lr = tid >> 3;            // 0..15
    const int lc = (tid & 7) * 4;       // 0..28

    const float* wbase = W13 + (size_t)e * 2 * INTER * HIDDEN;

    // token ids for the 8 A rows this thread loads (-1 -> zero-fill)
    int tok[8];
#pragma unroll
    for (int i = 0; i < 8; i++) {
        int r = row0 + lr + 16 * i;
        tok[i] = (r < ne) ? g_tok[e][r] : -1;
    }

    float accG[4][4][4], accU[4][4][4];
#pragma unroll
    for (int mt = 0; mt < 4; mt++)
#pragma unroll
        for (int nt = 0; nt < 4; nt++)
#pragma unroll
            for (int i = 0; i < 4; i++) { accG[mt][nt][i] = 0.f; accU[mt][nt][i] = 0.f; }

    auto issue = [&](int buf, int k0) {
        uint32_t da = smBase + (uint32_t)(buf * G1_BUF + lr * SA + lc) * 4u;
        uint32_t dg = smBase + (uint32_t)(buf * G1_BUF + (128 + lr) * SA + lc) * 4u;
        uint32_t du = smBase + (uint32_t)(buf * G1_BUF + (128 + 64 + lr) * SA + lc) * 4u;
#pragma unroll
        for (int i = 0; i < 8; i++) {
            bool v = tok[i] >= 0;
            const float* src = X + (size_t)(v ? tok[i] : 0) * HIDDEN + k0 + lc;
            cp16(da + (uint32_t)(i * 16 * SA) * 4u, src, v);
        }
#pragma unroll
        for (int i = 0; i < 4; i++) {
            cp16(dg + (uint32_t)(i * 16 * SA) * 4u,
                 wbase + (size_t)(col0 + lr + 16 * i) * HIDDEN + k0 + lc, true);
            cp16(du + (uint32_t)(i * 16 * SA) * 4u,
                 wbase + (size_t)(col0 + lr + 16 * i + INTER) * HIDDEN + k0 + lc, true);
        }
    };

    const int NIT = HIDDEN / BK;   // 64
    issue(0, 0);
    cp_commit();

    for (int it = 0; it < NIT; it++) {
        const int cur = it & 1;
        if (it + 1 < NIT) issue(cur ^ 1, (it + 1) * BK);
        cp_commit();
        cp_wait1();
        __syncthreads();

        const float* A  = sm + cur * G1_BUF;
        const float* Bg = A + 128 * SA;
        const float* Bu = Bg + 64 * SA;
#pragma unroll
        for (int kk = 0; kk < 4; kk++) {
            const int kb = kk * 8;
            uint32_t a[4][4];
#pragma unroll
            for (int mt = 0; mt < 4; mt++) {
                int ar = wm + mt * 16;
                a[mt][0] = f2tf32(A[(ar + g) * SA + kb + t4]);
                a[mt][1] = f2tf32(A[(ar + g + 8) * SA + kb + t4]);
                a[mt][2] = f2tf32(A[(ar + g) * SA + kb + t4 + 4]);
                a[mt][3] = f2tf32(A[(ar + g + 8) * SA + kb + t4 + 4]);
            }
#pragma unroll
            for (int nt = 0; nt < 4; nt++) {
                int bc = wn + nt * 8 + g;
                uint32_t bg0 = f2tf32(Bg[bc * SA + kb + t4]);
                uint32_t bg1 = f2tf32(Bg[bc * SA + kb + t4 + 4]);
                uint32_t bu0 = f2tf32(Bu[bc * SA + kb + t4]);
                uint32_t bu1 = f2tf32(Bu[bc * SA + kb + t4 + 4]);
#pragma unroll
                for (int mt = 0; mt < 4; mt++) {
                    mma_tf32(accG[mt][nt], a[mt][0], a[mt][1], a[mt][2], a[mt][3], bg0, bg1);
                    mma_tf32(accU[mt][nt], a[mt][0], a[mt][1], a[mt][2], a[mt][3], bu0, bu1);
                }
            }
        }
        __syncthreads();
    }

    // epilogue: act = silu(gate) * up
    float* actbase = g_act + (size_t)e * TOKENS * INTER;
#pragma unroll
    for (int mt = 0; mt < 4; mt++) {
        int r_lo = row0 + wm + mt * 16 + g;
        int r_hi = r_lo + 8;
#pragma unroll
        for (int nt = 0; nt < 4; nt++) {
            int c = col0 + wn + nt * 8 + 2 * t4;
            if (r_lo < ne) {
                float g0 = accG[mt][nt][0], g1 = accG[mt][nt][1];
                float a0 = g0 / (1.f + __expf(-g0)) * accU[mt][nt][0];
                float a1 = g1 / (1.f + __expf(-g1)) * accU[mt][nt][1];
                *reinterpret_cast<float2*>(actbase + (size_t)r_lo * INTER + c) = make_float2(a0, a1);
            }
            if (r_hi < ne) {
                float g2 = accG[mt][nt][2], g3 = accG[mt][nt][3];
                float a2 = g2 / (1.f + __expf(-g2)) * accU[mt][nt][2];
                float a3 = g3 / (1.f + __expf(-g3)) * accU[mt][nt][3];
                *reinterpret_cast<float2*>(actbase + (size_t)r_hi * INTER + c) = make_float2(a2, a3);
            }
        }
    }
}

// =================================================================
// kernel 3: grouped GEMM2 (g_act @ W2^T) -> weighted atomic scatter
// BM=128, BN=128; 4 warps, warp tile 64x64.
// =================================================================
#define G2_BUF ((128 + 128) * SA)

__global__ void __launch_bounds__(NTH)
gemm2_kernel(const float* __restrict__ W2, float* __restrict__ out) {
    const int e = blockIdx.z;
    const int ne = g_count[e];
    const int row0 = blockIdx.y * 128;
    if (row0 >= ne) return;
    const int col0 = blockIdx.x * 128;

    extern __shared__ float sm[];
    const uint32_t smBase = (uint32_t)__cvta_generic_to_shared(sm);

    const int tid = threadIdx.x, warp = tid >> 5, lane = tid & 31;
    const int g = lane >> 2, t4 = lane & 3;
    const int wm = (warp >> 1) * 64, wn = (warp & 1) * 64;
    const int lr = tid >> 3;
    const int lc = (tid & 7) * 4;

    const float* abase = g_act + (size_t)e * TOKENS * INTER;
    const float* bbase = W2 + (size_t)e * HIDDEN * INTER;

    bool aval[8];
#pragma unroll
    for (int i = 0; i < 8; i++) aval[i] = (row0 + lr + 16 * i) < ne;

    float acc[4][8][4];
#pragma unroll
    for (int mt = 0; mt < 4; mt++)
#pragma unroll
        for (int nt = 0; nt < 8; nt++)
#pragma unroll
            for (int i = 0; i < 4; i++) acc[mt][nt][i] = 0.f;

    auto issue = [&](int buf, int k0) {
        uint32_t da = smBase + (uint32_t)(buf * G2_BUF + lr * SA + lc) * 4u;
        uint32_t db = smBase + (uint32_t)(buf * G2_BUF + (128 + lr) * SA + lc) * 4u;
#pragma unroll
        for (int i = 0; i < 8; i++)
            cp16(da + (uint32_t)(i * 16 * SA) * 4u,
                 abase + (size_t)(row0 + lr + 16 * i) * INTER + k0 + lc, aval[i]);
#pragma unroll
        for (int i = 0; i < 8; i++)
            cp16(db + (uint32_t)(i * 16 * SA) * 4u,
                 bbase + (size_t)(col0 + lr + 16 * i) * INTER + k0 + lc, true);
    };

    const int NIT = INTER / BK;   // 128
    issue(0, 0);
    cp_commit();

    for (int it = 0; it < NIT; it++) {
        const int cur = it & 1;
        if (it + 1 < NIT) issue(cur ^ 1, (it + 1) * BK);
        cp_commit();
        cp_wait1();
        __syncthreads();

        const float* A = sm + cur * G2_BUF;
        const float* B = A + 128 * SA;
#pragma unroll
        for (int kk = 0; kk < 4; kk++) {
            const int kb = kk * 8;
            uint32_t a[4][4];
#pragma unroll
            for (int mt = 0; mt < 4; mt++) {
                int ar = wm + mt * 16;
                a[mt][0] = f2tf32(A[(ar + g) * SA + kb + t4]);
                a[mt][1] = f2tf32(A[(ar + g + 8) * SA + kb + t4]);
                a[mt][2] = f2tf32(A[(ar + g) * SA + kb + t4 + 4]);
                a[mt][3] = f2tf32(A[(ar + g + 8) * SA + kb + t4 + 4]);
            }
#pragma unroll
            for (int nt = 0; nt < 8; nt++) {
                int bc = wn + nt * 8 + g;
                uint32_t b0 = f2tf32(B[bc * SA + kb + t4]);
                uint32_t b1 = f2tf32(B[bc * SA + kb + t4 + 4]);
#pragma unroll
                for (int mt = 0; mt < 4; mt++)
                    mma_tf32(acc[mt][nt], a[mt][0], a[mt][1], a[mt][2], a[mt][3], b0, b1);
            }
        }
        __syncthreads();
    }

    // epilogue: out[token, col] += w * acc
#pragma unroll
    for (int mt = 0; mt < 4; mt++) {
        int r_lo = row0 + wm + mt * 16 + g;
        int r_hi = r_lo + 8;
        int   tok_lo = 0, tok_hi = 0;
        float w_lo = 0.f, w_hi = 0.f;
        if (r_lo < ne) { tok_lo = g_tok[e][r_lo]; w_lo = g_w[e][r_lo]; }
        if (r_hi < ne) { tok_hi = g_tok[e][r_hi]; w_hi = g_w[e][r_hi]; }
#pragma unroll
        for (int nt = 0; nt < 8; nt++) {
            int c = col0 + wn + nt * 8 + 2 * t4;
            if (r_lo < ne) {
                atomicAdd(&out[(size_t)tok_lo * HIDDEN + c    ], w_lo * acc[mt][nt][0]);
                atomicAdd(&out[(size_t)tok_lo * HIDDEN + c + 1], w_lo * acc[mt][nt][1]);
            }
            if (r_hi < ne) {
                atomicAdd(&out[(size_t)tok_hi * HIDDEN + c    ], w_hi * acc[mt][nt][2]);
                atomicAdd(&out[(size_t)tok_hi * HIDDEN + c + 1], w_hi * acc[mt][nt][3]);
            }
        }
    }
}

// ---------------- launch ----------------
extern "C" void kernel_launch(void* const* d_in, const int* in_sizes, int n_in,
                              void* d_out, int out_size) {
    const float* X      = (const float*)d_in[0];
    const float* logits = (const float*)d_in[1];
    const float* W13    = (const float*)d_in[2];
    const float* W2     = (const float*)d_in[3];
    float* out = (float*)d_out;

    const int smem1 = 2 * G1_BUF * 4;   // 73,728 B
    const int smem2 = 2 * G2_BUF * 4;   // 73,728 B
    cudaFuncSetAttribute(gemm1_kernel, cudaFuncAttributeMaxDynamicSharedMemorySize, smem1);
    cudaFuncSetAttribute(gemm2_kernel, cudaFuncAttributeMaxDynamicSharedMemorySize, smem2);

    zero_kernel<<<(TOKENS * HIDDEN / 4) / 256, 256>>>(out);
    router_kernel<<<(TOKENS + 255) / 256, 256>>>(logits);

    dim3 g1(INTER / 64, TOKENS / 128, NEXP);
    gemm1_kernel<<<g1, NTH, smem1>>>(X, W13);

    dim3 g2(HIDDEN / 128, TOKENS / 128, NEXP);
    gemm2_kernel<<<g2, NTH, smem2>>>(W2, out);
}

// round 4
// speedup vs baseline: 2.3872x; 2.3872x over previous
#include <cuda_runtime.h>
#include <cstdint>
#include <cstddef>

#define TOKENS 1024
#define HIDDEN 2048
#define INTER  4096
#define NEXP   8
#define NTH    128
#define BK     32
#define STG_BYTES 32768
#define DYN_SMEM (3 * STG_BYTES + 1024)   // covers tcgen05 path; fallback uses first 72KB

#if defined(__CUDA_ARCH__) && defined(__CUDA_ARCH_FEAT_SM103_ALL)
#define USE_TC 1
#else
#define USE_TC 0
#endif

// ---------------- device scratch ----------------
__device__ int   g_count[NEXP];
__device__ int   g_tok[NEXP][TOKENS];
__device__ float g_w[NEXP][TOKENS];
__device__ float g_xg[(size_t)NEXP * TOKENS * HIDDEN];   // gathered + tf32-rounded X
__device__ float g_act[(size_t)NEXP * TOKENS * INTER];   // activations

// ---------------- common helpers ----------------
__device__ __forceinline__ uint32_t f2tf32(float f) {
    uint32_t u;
    asm("cvt.rna.tf32.f32 %0, %1;" : "=r"(u) : "f"(f));
    return u;
}
__device__ __forceinline__ uint32_t smem_u32(const void* p) {
    uint32_t a;
    asm("{ .reg .u64 t; cvta.to.shared.u64 t, %1; cvt.u32.u64 %0, t; }" : "=r"(a) : "l"(p));
    return a;
}
__device__ __forceinline__ void cp16(uint32_t dst, const float* src) {
    asm volatile("cp.async.cg.shared.global [%0], [%1], 16;\n" :: "r"(dst), "l"(src));
}
__device__ __forceinline__ void cp16p(uint32_t dst, const float* src, bool pred) {
    int sz = pred ? 16 : 0;
    asm volatile("cp.async.cg.shared.global [%0], [%1], 16, %2;\n" :: "r"(dst), "l"(src), "r"(sz));
}
__device__ __forceinline__ void cp_commit() { asm volatile("cp.async.commit_group;\n"); }
template <int N> __device__ __forceinline__ void cp_wait() {
    asm volatile("cp.async.wait_group %0;\n" :: "n"(N) : "memory");
}

// ---------------- kernel 0: zero out + counts ----------------
__global__ void zero_kernel(float* __restrict__ out) {
    int i = blockIdx.x * blockDim.x + threadIdx.x;
    reinterpret_cast<float4*>(out)[i] = make_float4(0.f, 0.f, 0.f, 0.f);
    if (blockIdx.x == 0 && threadIdx.x < NEXP) g_count[threadIdx.x] = 0;
}

// ---------------- kernel 1: router ----------------
__global__ void router_kernel(const float* __restrict__ logits) {
    int t = blockIdx.x * blockDim.x + threadIdx.x;
    if (t >= TOKENS) return;
    float l[NEXP];
#pragma unroll
    for (int j = 0; j < NEXP; j++) l[j] = logits[t * NEXP + j];
    int i0 = 0;
#pragma unroll
    for (int j = 1; j < NEXP; j++) if (l[j] > l[i0]) i0 = j;
    int i1 = -1;
#pragma unroll
    for (int j = 0; j < NEXP; j++) {
        if (j == i0) continue;
        if (i1 < 0 || l[j] > l[i1]) i1 = j;
    }
    float e1 = __expf(l[i1] - l[i0]);
    float w1 = e1 / (1.f + e1);
    float w0 = 1.f / (1.f + e1);
    int p0 = atomicAdd(&g_count[i0], 1);
    g_tok[i0][p0] = t;  g_w[i0][p0] = w0;
    int p1 = atomicAdd(&g_count[i1], 1);
    g_tok[i1][p1] = t;  g_w[i1][p1] = w1;
}

// ---------------- kernel 2: gather + tf32-round X per expert slot ----------------
__global__ void gather_kernel(const float* __restrict__ X) {
    int row = blockIdx.x, e = blockIdx.y;
    if (row >= g_count[e]) return;
    int tok = g_tok[e][row];
    const float4* src = reinterpret_cast<const float4*>(X + (size_t)tok * HIDDEN);
    float4* dst = reinterpret_cast<float4*>(g_xg + ((size_t)e * TOKENS + row) * HIDDEN);
#pragma unroll
    for (int j = 0; j < 2; j++) {
        float4 v = src[threadIdx.x + 256 * j];
        v.x = __uint_as_float(f2tf32(v.x)); v.y = __uint_as_float(f2tf32(v.y));
        v.z = __uint_as_float(f2tf32(v.z)); v.w = __uint_as_float(f2tf32(v.w));
        dst[threadIdx.x + 256 * j] = v;
    }
}

#if USE_TC
// =================================================================
// tcgen05 path (compiled only for compute_103a virtual arch)
// =================================================================
#define MMA_IDESC ((1u<<4)|(2u<<7)|(2u<<10)|((128u/8)<<17)|((128u/16)<<24))

__device__ __forceinline__ uint32_t elect_one() {
    uint32_t p;
    asm volatile("{\n\t.reg .pred p;\n\telect.sync _|p, 0xFFFFFFFF;\n\tselp.b32 %0, 1, 0, p;\n\t}" : "=r"(p));
    return p;
}
__device__ __forceinline__ uint32_t swz(uint32_t o) { return o ^ ((o >> 3) & 0x70); }

static constexpr uint64_t DESC_SW128 =
    (2ull << 61) | (1ull << 46) | (64ull << 32) | (1ull << 16);
__device__ __forceinline__ uint64_t mkdesc(uint32_t addr) {
    return DESC_SW128 | ((uint64_t)(addr >> 4) & 0x3FFF);
}
__device__ __forceinline__ void mma_ss_tf32(uint32_t d, uint64_t ad, uint64_t bd,
                                            uint32_t idesc, bool en) {
    uint32_t e = en ? 1u : 0u;
    asm volatile(
        "{\n\t.reg .pred p;\n\tsetp.ne.u32 p, %4, 0;\n\t"
        "tcgen05.mma.cta_group::1.kind::tf32 [%0], %1, %2, %3, p;\n\t}"
        :: "r"(d), "l"(ad), "l"(bd), "r"(idesc), "r"(e) : "memory");
}
#define MBAR_INIT(a, c)  asm volatile("mbarrier.init.shared.b64 [%0], %1;" :: "r"(a), "r"(c) : "memory")
#define TC_COMMIT(a)     asm volatile("tcgen05.commit.cta_group::1.mbarrier::arrive::one.shared::cluster.b64 [%0];" :: "r"(a) : "memory")
#define TC_ALLOC(a, n)   asm volatile("tcgen05.alloc.cta_group::1.sync.aligned.shared::cta.b32 [%0], %1;" :: "r"(a), "r"(n) : "memory")
#define TC_RELINQ()      asm volatile("tcgen05.relinquish_alloc_permit.cta_group::1.sync.aligned;")
#define TC_DEALLOC(t, n) asm volatile("tcgen05.dealloc.cta_group::1.sync.aligned.b32 %0, %1;" :: "r"(t), "r"(n))
#define TC_WAIT_LD()     asm volatile("tcgen05.wait::ld.sync.aligned;" ::: "memory")
#define TC_FENCE_AFTER() asm volatile("tcgen05.fence::after_thread_sync;" ::: "memory")
#define FENCE_ASYNC()    asm volatile("fence.proxy.async.shared::cta;" ::: "memory")
#define MBAR_WAIT(mbar, par) do {                                              \
    uint32_t _m = (mbar), _p = (par);                                          \
    asm volatile(                                                              \
        "{\n\t.reg .pred P1;\n\t"                                             \
        "WL_%=:\n\t"                                                          \
        "mbarrier.try_wait.parity.acquire.cta.shared::cta.b64 P1, [%0], %1, 0x989680;\n\t" \
        "@P1 bra.uni WD_%=;\n\t"                                              \
        "bra.uni WL_%=;\n\t"                                                  \
        "WD_%=:\n\t}"                                                         \
        :: "r"(_m), "r"(_p) : "memory");                                       \
} while (0)
#define TC_LD_X32(r, a)                                                        \
    asm volatile("tcgen05.ld.sync.aligned.32x32b.x32.b32 "                     \
        "{%0,%1,%2,%3,%4,%5,%6,%7,%8,%9,%10,%11,%12,%13,%14,%15,"              \
        "%16,%17,%18,%19,%20,%21,%22,%23,%24,%25,%26,%27,%28,%29,%30,%31}, [%32];" \
        : "=r"((r)[0]),"=r"((r)[1]),"=r"((r)[2]),"=r"((r)[3]),                  \
          "=r"((r)[4]),"=r"((r)[5]),"=r"((r)[6]),"=r"((r)[7]),                  \
          "=r"((r)[8]),"=r"((r)[9]),"=r"((r)[10]),"=r"((r)[11]),                \
          "=r"((r)[12]),"=r"((r)[13]),"=r"((r)[14]),"=r"((r)[15]),              \
          "=r"((r)[16]),"=r"((r)[17]),"=r"((r)[18]),"=r"((r)[19]),              \
          "=r"((r)[20]),"=r"((r)[21]),"=r"((r)[22]),"=r"((r)[23]),              \
          "=r"((r)[24]),"=r"((r)[25]),"=r"((r)[26]),"=r"((r)[27]),              \
          "=r"((r)[28]),"=r"((r)[29]),"=r"((r)[30]),"=r"((r)[31])               \
        : "r"(a))

__global__ void __launch_bounds__(NTH)
gemm1_kernel(const float* __restrict__ X, const float* __restrict__ W13) {
    const int e = blockIdx.z;
    const int ne = g_count[e];
    const int row0 = blockIdx.y * 128;
    if (row0 >= ne) return;
    const int col0 = blockIdx.x * 64;

    extern __shared__ char dynsm[];
    __shared__ uint32_t s_tmem;
    __shared__ __align__(8) uint64_t s_mbar;
    char* smA = (char*)(((uintptr_t)dynsm + 1023) & ~(uintptr_t)1023);
    const uint32_t smA_u = smem_u32(smA);

    const int tid = threadIdx.x, warp = tid >> 5, lane = tid & 31;
    if (tid == 0) MBAR_INIT(smem_u32(&s_mbar), 1);
    if (warp == 0) { TC_ALLOC(smem_u32(&s_tmem), 128); TC_RELINQ(); }
    __syncthreads();
    const uint32_t tmem = s_tmem;
    const uint32_t mbar = smem_u32(&s_mbar);

    const float* aBase = g_xg + ((size_t)e * TOKENS + row0) * HIDDEN;
    const float* wBase = W13 + (size_t)e * (2 * INTER) * HIDDEN;

    auto issue = [&](int p, int k0) {
        uint32_t dA = smA_u + p * STG_BYTES;
        uint32_t dB = dA + 16384;
#pragma unroll
        for (int j = 0; j < 8; j++) {
            int i = tid + NTH * j, r = i >> 3, c = i & 7;
            cp16(dA + swz(r * 128 + c * 16), aBase + (size_t)r * HIDDEN + k0 + c * 4);
            int grow = (r < 64) ? (col0 + r) : (INTER + col0 + r - 64);
            cp16(dB + swz(r * 128 + c * 16), wBase + (size_t)grow * HIDDEN + k0 + c * 4);
        }
        cp_commit();
    };

    issue(0, 0); issue(1, BK); issue(2, 2 * BK);

    const int NS = HIDDEN / BK;  // 64
    for (int s = 0; s < NS; s++) {
        const int p = s % 3;
        if (s <= NS - 3)      cp_wait<2>();
        else if (s == NS - 2) cp_wait<1>();
        else                  cp_wait<0>();
        __syncthreads();

        float4* B4 = (float4*)(smA + p * STG_BYTES + 16384);
#pragma unroll
        for (int j = 0; j < 8; j++) {
            float4 v = B4[tid + NTH * j];
            v.x = __uint_as_float(f2tf32(v.x)); v.y = __uint_as_float(f2tf32(v.y));
            v.z = __uint_as_float(f2tf32(v.z)); v.w = __uint_as_float(f2tf32(v.w));
            B4[tid + NTH * j] = v;
        }
        __syncthreads();
        FENCE_ASYNC();

        if (warp == 0 && elect_one()) {
            uint64_t ad = mkdesc(smA_u + p * STG_BYTES);
            uint64_t bd = mkdesc(smA_u + p * STG_BYTES + 16384);
#pragma unroll
            for (int k = 0; k < 4; k++)
                mma_ss_tf32(tmem, ad + 2 * k, bd + 2 * k, MMA_IDESC, !(s == 0 && k == 0));
            TC_COMMIT(mbar);
        }
        MBAR_WAIT(mbar, s & 1);
        if (s + 3 < NS) issue(p, (s + 3) * BK);
    }
    TC_FENCE_AFTER();

    // epilogue: act = silu(gate)*up (tf32-rounded); warp w = rows row0+32w..+31
    const int slot = row0 + warp * 32 + lane;
#pragma unroll
    for (int pass = 0; pass < 2; pass++) {
        uint32_t gr[32], ur[32];
        TC_LD_X32(gr, tmem + 32 * pass);
        TC_LD_X32(ur, tmem + 64 + 32 * pass);
        TC_WAIT_LD();
        if (slot < ne) {
            float* dst = g_act + ((size_t)e * TOKENS + slot) * INTER + col0 + 32 * pass;
#pragma unroll
            for (int c = 0; c < 32; c += 4) {
                float4 o;
#pragma unroll
                for (int q = 0; q < 4; q++) {
                    float gg = __uint_as_float(gr[c + q]);
                    float uu = __uint_as_float(ur[c + q]);
                    float a = gg / (1.f + __expf(-gg)) * uu;
                    (&o.x)[q] = __uint_as_float(f2tf32(a));
                }
                *reinterpret_cast<float4*>(dst + c) = o;
            }
        }
    }
    __syncthreads();
    if (warp == 0) TC_DEALLOC(tmem, 128);
}

__global__ void __launch_bounds__(NTH)
gemm2_kernel(const float* __restrict__ W2, float* __restrict__ out) {
    const int e = blockIdx.z;
    const int ne = g_count[e];
    const int row0 = blockIdx.y * 128;
    if (row0 >= ne) return;
    const int col0 = blockIdx.x * 128;

    extern __shared__ char dynsm[];
    __shared__ uint32_t s_tmem;
    __shared__ __align__(8) uint64_t s_mbar;
    char* smA = (char*)(((uintptr_t)dynsm + 1023) & ~(uintptr_t)1023);
    const uint32_t smA_u = smem_u32(smA);

    const int tid = threadIdx.x, warp = tid >> 5, lane = tid & 31;
    if (tid == 0) MBAR_INIT(smem_u32(&s_mbar), 1);
    if (warp == 0) { TC_ALLOC(smem_u32(&s_tmem), 128); TC_RELINQ(); }
    __syncthreads();
    const uint32_t tmem = s_tmem;
    const uint32_t mbar = smem_u32(&s_mbar);

    const float* aBase = g_act + ((size_t)e * TOKENS + row0) * INTER;
    const float* bBase = W2 + (size_t)e * HIDDEN * INTER;

    auto issue = [&](int p, int k0) {
        uint32_t dA = smA_u + p * STG_BYTES;
        uint32_t dB = dA + 16384;
#pragma unroll
        for (int j = 0; j < 8; j++) {
            int i = tid + NTH * j, r = i >> 3, c = i & 7;
            cp16(dA + swz(r * 128 + c * 16), aBase + (size_t)r * INTER + k0 + c * 4);
            cp16(dB + swz(r * 128 + c * 16), bBase + (size_t)(col0 + r) * INTER + k0 + c * 4);
        }
        cp_commit();
    };

    issue(0, 0); issue(1, BK); issue(2, 2 * BK);

    const int NS = INTER / BK;  // 128
    for (int s = 0; s < NS; s++) {
        const int p = s % 3;
        if (s <= NS - 3)      cp_wait<2>();
        else if (s == NS - 2) cp_wait<1>();
        else                  cp_wait<0>();
        __syncthreads();

        float4* B4 = (float4*)(smA + p * STG_BYTES + 16384);
#pragma unroll
        for (int j = 0; j < 8; j++) {
            float4 v = B4[tid + NTH * j];
            v.x = __uint_as_float(f2tf32(v.x)); v.y = __uint_as_float(f2tf32(v.y));
            v.z = __uint_as_float(f2tf32(v.z)); v.w = __uint_as_float(f2tf32(v.w));
            B4[tid + NTH * j] = v;
        }
        __syncthreads();
        FENCE_ASYNC();

        if (warp == 0 && elect_one()) {
            uint64_t ad = mkdesc(smA_u + p * STG_BYTES);
            uint64_t bd = mkdesc(smA_u + p * STG_BYTES + 16384);
#pragma unroll
            for (int k = 0; k < 4; k++)
                mma_ss_tf32(tmem, ad + 2 * k, bd + 2 * k, MMA_IDESC, !(s == 0 && k == 0));
            TC_COMMIT(mbar);
        }
        MBAR_WAIT(mbar, s & 1);
        if (s + 3 < NS) issue(p, (s + 3) * BK);
    }
    TC_FENCE_AFTER();

    // epilogue: out[token] += w * D ; warp w = rows row0+32w..+31
    const int slot = row0 + warp * 32 + lane;
    int tok = 0; float w = 0.f;
    if (slot < ne) { tok = g_tok[e][slot]; w = g_w[e][slot]; }
#pragma unroll
    for (int pass = 0; pass < 4; pass++) {
        uint32_t d[32];
        TC_LD_X32(d, tmem + 32 * pass);
        TC_WAIT_LD();
        if (slot < ne) {
            float* o = out + (size_t)tok * HIDDEN + col0 + 32 * pass;
#pragma unroll
            for (int c = 0; c < 32; c++) atomicAdd(o + c, w * __uint_as_float(d[c]));
        }
    }
    __syncthreads();
    if (warp == 0) TC_DEALLOC(tmem, 128);
}

#else
// =================================================================
// Fallback path (compute_103 / no tcgen05): round-2 mma.sync kernels
// =================================================================
#define SA 36
#define G1_BUF ((128 + 64 + 64) * SA)
#define G2_BUF ((128 + 128) * SA)

__device__ __forceinline__ void mma_tf32(float c[4],
                                         uint32_t a0, uint32_t a1, uint32_t a2, uint32_t a3,
                                         uint32_t b0, uint32_t b1) {
    asm volatile(
        "mma.sync.aligned.m16n8k8.row.col.f32.tf32.tf32.f32 "
        "{%0,%1,%2,%3}, {%4,%5,%6,%7}, {%8,%9}, {%0,%1,%2,%3};\n"
        : "+f"(c[0]), "+f"(c[1]), "+f"(c[2]), "+f"(c[3])
        : "r"(a0), "r"(a1), "r"(a2), "r"(a3), "r"(b0), "r"(b1));
}

__global__ void __launch_bounds__(NTH)
gemm1_kernel(const float* __restrict__ X, const float* __restrict__ W13) {
    const int e = blockIdx.z;
    const int ne = g_count[e];
    const int row0 = blockIdx.y * 128;
    if (row0 >= ne) return;
    const int col0 = blockIdx.x * 64;

    extern __shared__ float sm[];
    const uint32_t smBase = (uint32_t)__cvta_generic_to_shared(sm);

    const int tid = threadIdx.x, warp = tid >> 5, lane = tid & 31;
    const int g = lane >> 2, t4 = lane & 3;
    const int wm = (warp >> 1) * 64, wn = (warp & 1) * 32;
    const int lr = tid >> 3;
    const int lc = (tid & 7) * 4;

    const float* wbase = W13 + (size_t)e * 2 * INTER * HIDDEN;

    int tok[8];
#pragma unroll
    for (int i = 0; i < 8; i++) {
        int r = row0 + lr + 16 * i;
        tok[i] = (r < ne) ? g_tok[e][r] : -1;
    }

    float accG[4][4][4], accU[4][4][4];
#pragma unroll
    for (int mt = 0; mt < 4; mt++)
#pragma unroll
        for (int nt = 0; nt < 4; nt++)
#pragma unroll
            for (int i = 0; i < 4; i++) { accG[mt][nt][i] = 0.f; accU[mt][nt][i] = 0.f; }

    auto issue = [&](int buf, int k0) {
        uint32_t da = smBase + (uint32_t)(buf * G1_BUF + lr * SA + lc) * 4u;
        uint32_t dg = smBase + (uint32_t)(buf * G1_BUF + (128 + lr) * SA + lc) * 4u;
        uint32_t du = smBase + (uint32_t)(buf * G1_BUF + (128 + 64 + lr) * SA + lc) * 4u;
#pragma unroll
        for (int i = 0; i < 8; i++) {
            bool v = tok[i] >= 0;
            const float* src = X + (size_t)(v ? tok[i] : 0) * HIDDEN + k0 + lc;
            cp16p(da + (uint32_t)(i * 16 * SA) * 4u, src, v);
        }
#pragma unroll
        for (int i = 0; i < 4; i++) {
            cp16p(dg + (uint32_t)(i * 16 * SA) * 4u,
                  wbase + (size_t)(col0 + lr + 16 * i) * HIDDEN + k0 + lc, true);
            cp16p(du + (uint32_t)(i * 16 * SA) * 4u,
                  wbase + (size_t)(col0 + lr + 16 * i + INTER) * HIDDEN + k0 + lc, true);
        }
    };

    const int NIT = HIDDEN / BK;
    issue(0, 0);
    cp_commit();

    for (int it = 0; it < NIT; it++) {
        const int cur = it & 1;
        if (it + 1 < NIT) issue(cur ^ 1, (it + 1) * BK);
        cp_commit();
        cp_wait<1>();
        __syncthreads();

        const float* A  = sm + cur * G1_BUF;
        const float* Bg = A + 128 * SA;
        const float* Bu = Bg + 64 * SA;
#pragma unroll
        for (int kk = 0; kk < 4; kk++) {
            const int kb = kk * 8;
            uint32_t a[4][4];
#pragma unroll
            for (int mt = 0; mt < 4; mt++) {
                int ar = wm + mt * 16;
                a[mt][0] = f2tf32(A[(ar + g) * SA + kb + t4]);
                a[mt][1] = f2tf32(A[(ar + g + 8) * SA + kb + t4]);
                a[mt][2] = f2tf32(A[(ar + g) * SA + kb + t4 + 4]);
                a[mt][3] = f2tf32(A[(ar + g + 8) * SA + kb + t4 + 4]);
            }
#pragma unroll
            for (int nt = 0; nt < 4; nt++) {
                int bc = wn + nt * 8 + g;
                uint32_t bg0 = f2tf32(Bg[bc * SA + kb + t4]);
                uint32_t bg1 = f2tf32(Bg[bc * SA + kb + t4 + 4]);
                uint32_t bu0 = f2tf32(Bu[bc * SA + kb + t4]);
                uint32_t bu1 = f2tf32(Bu[bc * SA + kb + t4 + 4]);
#pragma unroll
                for (int mt = 0; mt < 4; mt++) {
                    mma_tf32(accG[mt][nt], a[mt][0], a[mt][1], a[mt][2], a[mt][3], bg0, bg1);
                    mma_tf32(accU[mt][nt], a[mt][0], a[mt][1], a[mt][2], a[mt][3], bu0, bu1);
                }
            }
        }
        __syncthreads();
    }

    float* actbase = g_act + (size_t)e * TOKENS * INTER;
#pragma unroll
    for (int mt = 0; mt < 4; mt++) {
        int r_lo = row0 + wm + mt * 16 + g;
        int r_hi = r_lo + 8;
#pragma unroll
        for (int nt = 0; nt < 4; nt++) {
            int c = col0 + wn + nt * 8 + 2 * t4;
            if (r_lo < ne) {
                float g0 = accG[mt][nt][0], g1 = accG[mt][nt][1];
                float a0 = g0 / (1.f + __expf(-g0)) * accU[mt][nt][0];
                float a1 = g1 / (1.f + __expf(-g1)) * accU[mt][nt][1];
                *reinterpret_cast<float2*>(actbase + (size_t)r_lo * INTER + c) = make_float2(a0, a1);
            }
            if (r_hi < ne) {
                float g2 = accG[mt][nt][2], g3 = accG[mt][nt][3];
                float a2 = g2 / (1.f + __expf(-g2)) * accU[mt][nt][2];
                float a3 = g3 / (1.f + __expf(-g3)) * accU[mt][nt][3];
                *reinterpret_cast<float2*>(actbase + (size_t)r_hi * INTER + c) = make_float2(a2, a3);
            }
        }
    }
}

__global__ void __launch_bounds__(NTH)
gemm2_kernel(const float* __restrict__ W2, float* __restrict__ out) {
    const int e = blockIdx.z;
    const int ne = g_count[e];
    const int row0 = blockIdx.y * 128;
    if (row0 >= ne) return;
    const int col0 = blockIdx.x * 128;

    extern __shared__ float sm[];
    const uint32_t smBase = (uint32_t)__cvta_generic_to_shared(sm);

    const int tid = threadIdx.x, warp = tid >> 5, lane = tid & 31;
    const int g = lane >> 2, t4 = lane & 3;
    const int wm = (warp >> 1) * 64, wn = (warp & 1) * 64;
    const int lr = tid >> 3;
    const int lc = (tid & 7) * 4;

    const float* abase = g_act + (size_t)e * TOKENS * INTER;
    const float* bbase = W2 + (size_t)e * HIDDEN * INTER;

    bool aval[8];
#pragma unroll
    for (int i = 0; i < 8; i++) aval[i] = (row0 + lr + 16 * i) < ne;

    float acc[4][8][4];
#pragma unroll
    for (int mt = 0; mt < 4; mt++)
#pragma unroll
        for (int nt = 0; nt < 8; nt++)
#pragma unroll
            for (int i = 0; i < 4; i++) acc[mt][nt][i] = 0.f;

    auto issue = [&](int buf, int k0) {
        uint32_t da = smBase + (uint32_t)(buf * G2_BUF + lr * SA + lc) * 4u;
        uint32_t db = smBase + (uint32_t)(buf * G2_BUF + (128 + lr) * SA + lc) * 4u;
#pragma unroll
        for (int i = 0; i < 8; i++)
            cp16p(da + (uint32_t)(i * 16 * SA) * 4u,
                  abase + (size_t)(row0 + lr + 16 * i) * INTER + k0 + lc, aval[i]);
#pragma unroll
        for (int i = 0; i < 8; i++)
            cp16p(db + (uint32_t)(i * 16 * SA) * 4u,
                  bbase + (size_t)(col0 + lr + 16 * i) * INTER + k0 + lc, true);
    };

    const int NIT = INTER / BK;
    issue(0, 0);
    cp_commit();

    for (int it = 0; it < NIT; it++) {
        const int cur = it & 1;
        if (it + 1 < NIT) issue(cur ^ 1, (it + 1) * BK);
        cp_commit();
        cp_wait<1>();
        __syncthreads();

        const float* A = sm + cur * G2_BUF;
        const float* B = A + 128 * SA;
#pragma unroll
        for (int kk = 0; kk < 4; kk++) {
            const int kb = kk * 8;
            uint32_t a[4][4];
#pragma unroll
            for (int mt = 0; mt < 4; mt++) {
                int ar = wm + mt * 16;
                a[mt][0] = f2tf32(A[(ar + g) * SA + kb + t4]);
                a[mt][1] = f2tf32(A[(ar + g + 8) * SA + kb + t4]);
                a[mt][2] = f2tf32(A[(ar + g) * SA + kb + t4 + 4]);
                a[mt][3] = f2tf32(A[(ar + g + 8) * SA + kb + t4 + 4]);
            }
#pragma unroll
            for (int nt = 0; nt < 8; nt++) {
                int bc = wn + nt * 8 + g;
                uint32_t b0 = f2tf32(B[bc * SA + kb + t4]);
                uint32_t b1 = f2tf32(B[bc * SA + kb + t4 + 4]);
#pragma unroll
                for (int mt = 0; mt < 4; mt++)
                    mma_tf32(acc[mt][nt], a[mt][0], a[mt][1], a[mt][2], a[mt][3], b0, b1);
            }
        }
        __syncthreads();
    }

#pragma unroll
    for (int mt = 0; mt < 4; mt++) {
        int r_lo = row0 + wm + mt * 16 + g;
        int r_hi = r_lo + 8;
        int   tok_lo = 0, tok_hi = 0;
        float w_lo = 0.f, w_hi = 0.f;
        if (r_lo < ne) { tok_lo = g_tok[e][r_lo]; w_lo = g_w[e][r_lo]; }
        if (r_hi < ne) { tok_hi = g_tok[e][r_hi]; w_hi = g_w[e][r_hi]; }
#pragma unroll
        for (int nt = 0; nt < 8; nt++) {
            int c = col0 + wn + nt * 8 + 2 * t4;
            if (r_lo < ne) {
                atomicAdd(&out[(size_t)tok_lo * HIDDEN + c    ], w_lo * acc[mt][nt][0]);
                atomicAdd(&out[(size_t)tok_lo * HIDDEN + c + 1], w_lo * acc[mt][nt][1]);
            }
            if (r_hi < ne) {
                atomicAdd(&out[(size_t)tok_hi * HIDDEN + c    ], w_hi * acc[mt][nt][2]);
                atomicAdd(&out[(size_t)tok_hi * HIDDEN + c + 1], w_hi * acc[mt][nt][3]);
            }
        }
    }
}
#endif  // USE_TC

// ---------------- launch ----------------
extern "C" void kernel_launch(void* const* d_in, const int* in_sizes, int n_in,
                              void* d_out, int out_size) {
    const float* X      = (const float*)d_in[0];
    const float* logits = (const float*)d_in[1];
    const float* W13    = (const float*)d_in[2];
    const float* W2     = (const float*)d_in[3];
    float* out = (float*)d_out;

    cudaFuncSetAttribute(gemm1_kernel, cudaFuncAttributeMaxDynamicSharedMemorySize, DYN_SMEM);
    cudaFuncSetAttribute(gemm2_kernel, cudaFuncAttributeMaxDynamicSharedMemorySize, DYN_SMEM);

    zero_kernel<<<(TOKENS * HIDDEN / 4) / 256, 256>>>(out);
    router_kernel<<<(TOKENS + 255) / 256, 256>>>(logits);

    dim3 gg(TOKENS, NEXP);
    gather_kernel<<<gg, 256>>>(X);

    dim3 g1(INTER / 64, TOKENS / 128, NEXP);
    gemm1_kernel<<<g1, NTH, DYN_SMEM>>>(X, W13);

    dim3 g2(HIDDEN / 128, TOKENS / 128, NEXP);
    gemm2_kernel<<<g2, NTH, DYN_SMEM>>>(W2, out);
}